// round 6
// baseline (speedup 1.0000x reference)
#include <cuda_runtime.h>
#include <cuda_bf16.h>
#include <cuda_fp16.h>
#include <cstdint>

// Problem constants (fixed by setup_inputs)
#define KCL 65536      // number of clusters (GEMM N)
#define DD  256        // feature dim
#define OO  256        // output dim
#define BB  1024       // batch rows (GEMM M)
#define TOPK 32
#define KK  512        // GEMM reduction dim (2*DD)
#define CAND_CAP 2048

// ---------------- scratch (static device globals; no allocations) ----------
__device__ __nv_bfloat16 g_W[(size_t)KCL * KK];          // 64 MB
__device__ __nv_bfloat16 g_A[(size_t)BB * KK];           // 1 MB
__device__ float g_cterm[KCL];
__device__ float g_logn[KCL];
__device__ __half g_S[(size_t)BB * KCL];                 // 128 MB fp16 scores
__device__ unsigned g_rowmax[BB];
__device__ int g_cand[(size_t)BB * CAND_CAP];
__device__ int g_cnt[BB];

__device__ __forceinline__ unsigned fkey(float f) {
    unsigned u = __float_as_uint(f);
    return (u & 0x80000000u) ? ~u : (u | 0x80000000u);
}
__device__ __forceinline__ float keyf(unsigned k) {
    unsigned u = (k & 0x80000000u) ? (k & 0x7FFFFFFFu) : ~k;
    return __uint_as_float(u);
}

#define NEG_INF (__int_as_float(0xff800000))
#define LOG2PI 1.8378770664093455f

// ---------------- init --------------------------------------------------
__global__ void init_kernel() {
    int i = blockIdx.x * blockDim.x + threadIdx.x;
    if (i < BB) { g_rowmax[i] = 0u; g_cnt[i] = 0; }
}

// ---------------- prep A = [x*x, x] (bf16) ------------------------------
__global__ void prep_x_kernel(const float* __restrict__ x) {
    int b = blockIdx.x;
    int d = threadIdx.x;
    float v = x[b * DD + d];
    g_A[b * KK + d]      = __float2bfloat16(v * v);
    g_A[b * KK + DD + d] = __float2bfloat16(v);
}

// ---------------- prep W = [-0.5*ivar, mu*ivar], cterm, logn ------------
__global__ __launch_bounds__(256) void prep_w_kernel(const float* __restrict__ mean,
                                                     const float* __restrict__ stddev) {
    int k = blockIdx.x;
    int d = threadIdx.x;
    float mu = mean[k * DD + d];
    float sg = stddev[k * DD + d];
    float iv = __fdividef(1.0f, sg * sg);
    g_W[(size_t)k * KK + d]      = __float2bfloat16(-0.5f * iv);
    g_W[(size_t)k * KK + DD + d] = __float2bfloat16(mu * iv);

    float s1 = mu * mu * iv;
    float s2 = __logf(sg);
    #pragma unroll
    for (int o = 16; o; o >>= 1) {
        s1 += __shfl_xor_sync(0xffffffffu, s1, o);
        s2 += __shfl_xor_sync(0xffffffffu, s2, o);
    }
    __shared__ float sh1[8], sh2[8];
    int wid = threadIdx.x >> 5, lane = threadIdx.x & 31;
    if (lane == 0) { sh1[wid] = s1; sh2[wid] = s2; }
    __syncthreads();
    if (threadIdx.x == 0) {
        float t1 = 0.f, t2 = 0.f;
        #pragma unroll
        for (int i = 0; i < 8; i++) { t1 += sh1[i]; t2 += sh2[i]; }
        g_logn[k]  = t2;
        g_cterm[k] = -0.5f * t1 - t2 - 128.0f * LOG2PI;
    }
}

// ---------------- bf16 mma GEMM: S = A @ W^T + cterm --------------------
// 8 warps, warp grid 2 (M) x 4 (N), warp tile 64x64 -> frag smem traffic
// A x4 + B x2 copies (vs x2/x4 with 32x64 tiles at 16 warps, halved per MMA).
// 3-stage cp.async pipeline.
#define BM 128
#define BN 256
#define KC 64
#define NST 3
#define SA 72   // padded smem stride (elems); conflict-free ldmatrix

#define A_STG (BM * SA)                 // elems per A stage
#define W_STG (BN * SA)
#define W_BASE (NST * A_STG)            // layout: [A0][A1][A2][W0][W1][W2]
#define SMEM_BYTES ((NST * A_STG + NST * W_STG) * 2)

__device__ __forceinline__ void mma16816(float* c, const uint32_t* a, const uint32_t* b) {
    asm volatile(
        "mma.sync.aligned.m16n8k16.row.col.f32.bf16.bf16.f32 "
        "{%0,%1,%2,%3}, {%4,%5,%6,%7}, {%8,%9}, {%0,%1,%2,%3};\n"
        : "+f"(c[0]), "+f"(c[1]), "+f"(c[2]), "+f"(c[3])
        : "r"(a[0]), "r"(a[1]), "r"(a[2]), "r"(a[3]), "r"(b[0]), "r"(b[1]));
}

__device__ __forceinline__ void ldsm4(uint32_t& r0, uint32_t& r1, uint32_t& r2, uint32_t& r3,
                                      uint32_t addr) {
    asm volatile("ldmatrix.sync.aligned.m8n8.x4.shared.b16 {%0,%1,%2,%3}, [%4];\n"
                 : "=r"(r0), "=r"(r1), "=r"(r2), "=r"(r3) : "r"(addr));
}

__device__ __forceinline__ void cp_async16(uint32_t smem_dst, const void* gmem_src) {
    asm volatile("cp.async.cg.shared.global [%0], [%1], 16;\n" :: "r"(smem_dst), "l"(gmem_src));
}

__global__ __launch_bounds__(256, 1) void gemm_kernel() {
    extern __shared__ __nv_bfloat16 sh[];
    uint32_t smem_u32 = (uint32_t)__cvta_generic_to_shared(sh);

    int bm = blockIdx.x;              // 0..7   (fast dim -> W tile reused across bm in L2)
    int bn = blockIdx.y;              // 0..255
    int tid = threadIdx.x;
    int wid = tid >> 5, lane = tid & 31;
    int wm = wid & 1, wn = wid >> 1;  // warp tile: rows wm*64, cols wn*64
    int g = lane >> 2, t4 = lane & 3;

    // per-thread LDSM address components (bytes, relative to stage base)
    uint32_t aBase = (uint32_t)(((wm * 64 + (lane & 15)) * SA + (lane >> 4) * 8) * 2);
    uint32_t bBase = (uint32_t)(((wn * 64 + (lane & 7) + ((lane >> 4) << 3)) * SA
                                 + ((lane >> 3) & 1) * 8) * 2);

    int rA = tid >> 3;                // A rows step 32 per j (4 j)
    int cv = (tid & 7) * 8;           // col elems

    float acc[4][8][4];
    #pragma unroll
    for (int mt = 0; mt < 4; mt++)
        #pragma unroll
        for (int nt = 0; nt < 8; nt++)
            #pragma unroll
            for (int i = 0; i < 4; i++) acc[mt][nt][i] = 0.f;

    auto load_stage = [&](int kc, int st) {
        uint32_t aDst = smem_u32 + (uint32_t)(st * A_STG * 2);
        uint32_t wDst = smem_u32 + (uint32_t)((W_BASE + st * W_STG) * 2);
        #pragma unroll
        for (int j = 0; j < 4; j++) {
            int r = rA + j * 32;
            cp_async16(aDst + (uint32_t)((r * SA + cv) * 2),
                       &g_A[(size_t)(bm * BM + r) * KK + kc * KC + cv]);
        }
        #pragma unroll
        for (int j = 0; j < 8; j++) {
            int r = rA + j * 32;
            cp_async16(wDst + (uint32_t)((r * SA + cv) * 2),
                       &g_W[(size_t)(bn * BN + r) * KK + kc * KC + cv]);
        }
    };

    load_stage(0, 0);
    asm volatile("cp.async.commit_group;\n");
    load_stage(1, 1);
    asm volatile("cp.async.commit_group;\n");

    for (int kc = 0; kc < KK / KC; kc++) {
        asm volatile("cp.async.wait_group 1;\n");   // stage kc resident
        __syncthreads();
        if (kc + 2 < KK / KC) load_stage(kc + 2, (kc + 2) % NST);
        asm volatile("cp.async.commit_group;\n");   // always commit (group counting)

        int st = kc % NST;
        uint32_t aStage = smem_u32 + (uint32_t)(st * A_STG * 2) + aBase;
        uint32_t wStage = smem_u32 + (uint32_t)((W_BASE + st * W_STG) * 2) + bBase;

        #pragma unroll
        for (int s = 0; s < KC / 16; s++) {
            int kb = s * 16;
            uint32_t af[4][4], bfr[8][2];
            #pragma unroll
            for (int mt = 0; mt < 4; mt++)
                ldsm4(af[mt][0], af[mt][1], af[mt][2], af[mt][3],
                      aStage + (uint32_t)((mt * 16 * SA + kb) * 2));
            #pragma unroll
            for (int p = 0; p < 4; p++)
                ldsm4(bfr[2 * p][0], bfr[2 * p][1], bfr[2 * p + 1][0], bfr[2 * p + 1][1],
                      wStage + (uint32_t)((p * 16 * SA + kb) * 2));
            #pragma unroll
            for (int mt = 0; mt < 4; mt++)
                #pragma unroll
                for (int nt = 0; nt < 8; nt++)
                    mma16816(acc[mt][nt], af[mt], bfr[nt]);
        }
        // no trailing sync needed: stage st is only overwritten by the load
        // issued AFTER next iteration's __syncthreads()
    }

    // epilogue: add cterm, store fp16 scores, fold per-row max into global
    int n0 = bn * BN + wn * 64;
    float rmax[4][2];
    #pragma unroll
    for (int mt = 0; mt < 4; mt++) { rmax[mt][0] = NEG_INF; rmax[mt][1] = NEG_INF; }
    #pragma unroll
    for (int mt = 0; mt < 4; mt++) {
        int row0 = bm * BM + wm * 64 + mt * 16 + g;
        #pragma unroll
        for (int nt = 0; nt < 8; nt++) {
            int col = n0 + nt * 8 + t4 * 2;
            float2 ct = *(const float2*)&g_cterm[col];
            float v0 = acc[mt][nt][0] + ct.x;
            float v1 = acc[mt][nt][1] + ct.y;
            float v2 = acc[mt][nt][2] + ct.x;
            float v3 = acc[mt][nt][3] + ct.y;
            *(__half2*)&g_S[(size_t)row0 * KCL + col]       = __floats2half2_rn(v0, v1);
            *(__half2*)&g_S[(size_t)(row0 + 8) * KCL + col] = __floats2half2_rn(v2, v3);
            rmax[mt][0] = fmaxf(rmax[mt][0], fmaxf(v0, v1));
            rmax[mt][1] = fmaxf(rmax[mt][1], fmaxf(v2, v3));
        }
    }
    #pragma unroll
    for (int mt = 0; mt < 4; mt++)
        #pragma unroll
        for (int h = 0; h < 2; h++) {
            float v = rmax[mt][h];
            v = fmaxf(v, __shfl_xor_sync(0xffffffffu, v, 1));
            v = fmaxf(v, __shfl_xor_sync(0xffffffffu, v, 2));
            if (t4 == 0)
                atomicMax(&g_rowmax[bm * BM + wm * 64 + mt * 16 + h * 8 + g], fkey(v));
        }
}

// ---------------- candidate selection (per row, fp16 scores) -------------
__global__ __launch_bounds__(256) void select_kernel() {
    int b = blockIdx.x;
    int tid = threadIdx.x;
    __shared__ unsigned hist[2048];
    __shared__ int s_b32;
    __shared__ int s_cnt;
    for (int i = tid; i < 2048; i += 256) hist[i] = 0u;
    if (tid == 0) s_cnt = 0;
    __syncthreads();

    float M = keyf(g_rowmax[b]);
    const uint4* S4 = (const uint4*)&g_S[(size_t)b * KCL];   // 8 halves per load
    for (int i = tid; i < KCL / 8; i += 256) {
        uint4 u = S4[i];
        const __half2* h = (const __half2*)&u;
        #pragma unroll
        for (int p = 0; p < 4; p++) {
            float2 f = __half22float2(h[p]);
            float d0 = fmaxf(M - f.x, 0.f);
            float d1 = fmaxf(M - f.y, 0.f);
            if (d0 < 256.0f) atomicAdd(&hist[(int)(d0 * 8.0f)], 1u);
            if (d1 < 256.0f) atomicAdd(&hist[(int)(d1 * 8.0f)], 1u);
        }
    }
    __syncthreads();
    if (tid == 0) {
        unsigned cum = 0; int bidx = 2047;
        for (int i = 0; i < 2048; i++) { cum += hist[i]; if (cum >= TOPK) { bidx = i; break; } }
        s_b32 = bidx;
    }
    __syncthreads();
    float T = M - (float)(s_b32 + 1) * 0.125f - 3.0f;   // margin: bf16 gemm + fp16 store
    for (int i = tid; i < KCL / 8; i += 256) {
        uint4 u = S4[i];
        const __half2* h = (const __half2*)&u;
        #pragma unroll
        for (int p = 0; p < 4; p++) {
            float2 f = __half22float2(h[p]);
            if (f.x >= T) {
                int q = atomicAdd(&s_cnt, 1);
                if (q < CAND_CAP) g_cand[(size_t)b * CAND_CAP + q] = i * 8 + p * 2;
            }
            if (f.y >= T) {
                int q = atomicAdd(&s_cnt, 1);
                if (q < CAND_CAP) g_cand[(size_t)b * CAND_CAP + q] = i * 8 + p * 2 + 1;
            }
        }
    }
    __syncthreads();
    if (tid == 0) g_cnt[b] = min(s_cnt, CAND_CAP);
}

// ---------------- exact rescore + top-32 (rank count) + softmax + gather --
__global__ __launch_bounds__(256) void rescore_kernel(const float* __restrict__ x,
                                                      const float* __restrict__ mean,
                                                      const float* __restrict__ stddev,
                                                      const float* __restrict__ outputs,
                                                      float* __restrict__ out) {
    int b = blockIdx.x;
    int tid = threadIdx.x, wid = tid >> 5, lane = tid & 31;
    __shared__ float xs[DD];
    __shared__ float lp_s[CAND_CAP];
    __shared__ int   selk[TOPK];
    __shared__ float selw[TOPK];

    xs[tid] = x[b * DD + tid];
    int cnt = g_cnt[b];
    __syncthreads();

    // exact fp32 log-prob for each candidate (one warp per candidate)
    for (int j = wid; j < cnt; j += 8) {
        int k = g_cand[(size_t)b * CAND_CAP + j];
        float acc = 0.f;
        #pragma unroll
        for (int t = 0; t < 8; t++) {
            int d = lane + t * 32;
            float mu = mean[k * DD + d];
            float sg = stddev[k * DD + d];
            float iv = 1.0f / (sg * sg);
            float df = xs[d] - mu;
            acc += df * df * iv;
        }
        #pragma unroll
        for (int o = 16; o; o >>= 1) acc += __shfl_xor_sync(0xffffffffu, acc, o);
        if (lane == 0) lp_s[j] = -0.5f * acc - g_logn[k] - 128.0f * LOG2PI;
    }
    __syncthreads();

    // top-32 by rank counting: rank_i = #{ j : lp_j > lp_i (tie: j < i) }
    for (int i = tid; i < cnt; i += 256) {
        float v = lp_s[i];
        int rank = 0;
        for (int j = 0; j < cnt; j++) {
            float u = lp_s[j];
            rank += (u > v) || (u == v && j < i);
            if (rank >= TOPK) break;
        }
        if (rank < TOPK) {
            selk[rank] = g_cand[(size_t)b * CAND_CAP + i];
            selw[rank] = v;
        }
    }
    __syncthreads();

    // softmax over the 32 (rank 0 holds the max)
    if (tid == 0) {
        float m = selw[0], z = 0.f;
        #pragma unroll
        for (int i = 0; i < TOPK; i++) { float e = expf(selw[i] - m); selw[i] = e; z += e; }
        float iz = 1.0f / z;
        #pragma unroll
        for (int i = 0; i < TOPK; i++) selw[i] *= iz;
    }
    __syncthreads();

    // weighted gather: out[b, o] = sum_i w_i * outputs[k_i, o]
    float acc = 0.f;
    #pragma unroll 8
    for (int i = 0; i < TOPK; i++)
        acc += selw[i] * outputs[selk[i] * OO + tid];
    out[b * OO + tid] = acc;
}

// ---------------- launch -----------------------------------------------
extern "C" void kernel_launch(void* const* d_in, const int* in_sizes, int n_in,
                              void* d_out, int out_size) {
    const float* x       = (const float*)d_in[0];
    const float* mean    = (const float*)d_in[1];
    const float* stddev  = (const float*)d_in[2];
    const float* outputs = (const float*)d_in[3];
    float* out = (float*)d_out;
    (void)in_sizes; (void)n_in; (void)out_size;

    cudaFuncSetAttribute(gemm_kernel, cudaFuncAttributeMaxDynamicSharedMemorySize, SMEM_BYTES);

    init_kernel<<<4, 256>>>();
    prep_x_kernel<<<BB, 256>>>(x);
    prep_w_kernel<<<KCL, 256>>>(mean, stddev);
    gemm_kernel<<<dim3(BB / BM, KCL / BN), 256, SMEM_BYTES>>>();
    select_kernel<<<BB, 256>>>();
    rescore_kernel<<<BB, 256>>>(x, mean, stddev, outputs, out);
}

// round 9
// speedup vs baseline: 1.1849x; 1.1849x over previous
#include <cuda_runtime.h>
#include <cuda_bf16.h>
#include <cuda_fp16.h>
#include <cstdint>

// Problem constants (fixed by setup_inputs)
#define KCL 65536      // number of clusters (GEMM N)
#define DD  256        // feature dim
#define OO  256        // output dim
#define BB  1024       // batch rows (GEMM M)
#define TOPK 32
#define KK  512        // GEMM reduction dim (2*DD)
#define CAND_CAP 2048
#define NBLK (KCL / 64)    // 1024 score-blocks of 64 cols per row

// ---------------- scratch (static device globals; no allocations) ----------
__device__ __nv_bfloat16 g_W[(size_t)KCL * KK];          // 64 MB
__device__ __nv_bfloat16 g_A[(size_t)BB * KK];           // 1 MB
__device__ float g_cterm[KCL];
__device__ float g_logn[KCL];
__device__ __half g_S[(size_t)BB * KCL];                 // 128 MB fp16 scores
__device__ float g_blk[(size_t)BB * NBLK];               // 4 MB per-64col block maxima
__device__ int g_cand[(size_t)BB * CAND_CAP];
__device__ int g_cnt[BB];

#define NEG_INF (__int_as_float(0xff800000))
#define LOG2PI 1.8378770664093455f

// ---------------- prep A = [x*x, x] (bf16) ------------------------------
__global__ void prep_x_kernel(const float* __restrict__ x) {
    int b = blockIdx.x;
    int d = threadIdx.x;
    float v = x[b * DD + d];
    g_A[b * KK + d]      = __float2bfloat16(v * v);
    g_A[b * KK + DD + d] = __float2bfloat16(v);
}

// ---------------- prep W = [-0.5*ivar, mu*ivar], cterm, logn ------------
__global__ __launch_bounds__(256) void prep_w_kernel(const float* __restrict__ mean,
                                                     const float* __restrict__ stddev) {
    int k = blockIdx.x;
    int d = threadIdx.x;
    float mu = mean[k * DD + d];
    float sg = stddev[k * DD + d];
    float iv = __fdividef(1.0f, sg * sg);
    g_W[(size_t)k * KK + d]      = __float2bfloat16(-0.5f * iv);
    g_W[(size_t)k * KK + DD + d] = __float2bfloat16(mu * iv);

    float s1 = mu * mu * iv;
    float s2 = __logf(sg);
    #pragma unroll
    for (int o = 16; o; o >>= 1) {
        s1 += __shfl_xor_sync(0xffffffffu, s1, o);
        s2 += __shfl_xor_sync(0xffffffffu, s2, o);
    }
    __shared__ float sh1[8], sh2[8];
    int wid = threadIdx.x >> 5, lane = threadIdx.x & 31;
    if (lane == 0) { sh1[wid] = s1; sh2[wid] = s2; }
    __syncthreads();
    if (threadIdx.x == 0) {
        float t1 = 0.f, t2 = 0.f;
        #pragma unroll
        for (int i = 0; i < 8; i++) { t1 += sh1[i]; t2 += sh2[i]; }
        g_logn[k]  = t2;
        g_cterm[k] = -0.5f * t1 - t2 - 128.0f * LOG2PI;
    }
}

// ---------------- bf16 mma GEMM: S = A @ W^T + cterm --------------------
// R3 shape (8 warps... 16 warps/SM via 2 CTAs, 32x64 warp tiles) + 3-stage
// cp.async pipeline (no trailing per-chunk __syncthreads).
#define BM 128
#define BN 128
#define KC 64
#define NST 3
#define SA 72   // padded smem stride (elems); conflict-free ldmatrix

#define A_STG (BM * SA)                 // elems per A stage
#define W_STG (BN * SA)
#define W_BASE (NST * A_STG)            // layout: [A0][A1][A2][W0][W1][W2]
#define SMEM_BYTES ((NST * A_STG + NST * W_STG) * 2)   // 110,592 B -> 2 CTAs/SM

__device__ __forceinline__ void mma16816(float* c, const uint32_t* a, const uint32_t* b) {
    asm volatile(
        "mma.sync.aligned.m16n8k16.row.col.f32.bf16.bf16.f32 "
        "{%0,%1,%2,%3}, {%4,%5,%6,%7}, {%8,%9}, {%0,%1,%2,%3};\n"
        : "+f"(c[0]), "+f"(c[1]), "+f"(c[2]), "+f"(c[3])
        : "r"(a[0]), "r"(a[1]), "r"(a[2]), "r"(a[3]), "r"(b[0]), "r"(b[1]));
}

__device__ __forceinline__ void ldsm4(uint32_t& r0, uint32_t& r1, uint32_t& r2, uint32_t& r3,
                                      uint32_t addr) {
    asm volatile("ldmatrix.sync.aligned.m8n8.x4.shared.b16 {%0,%1,%2,%3}, [%4];\n"
                 : "=r"(r0), "=r"(r1), "=r"(r2), "=r"(r3) : "r"(addr));
}

__device__ __forceinline__ void cp_async16(uint32_t smem_dst, const void* gmem_src) {
    asm volatile("cp.async.cg.shared.global [%0], [%1], 16;\n" :: "r"(smem_dst), "l"(gmem_src));
}

__global__ __launch_bounds__(256, 2) void gemm_kernel() {
    extern __shared__ __nv_bfloat16 sh[];
    uint32_t smem_u32 = (uint32_t)__cvta_generic_to_shared(sh);

    int bm = blockIdx.x;              // 0..7   (fast dim -> W tile reused across bm in L2)
    int bn = blockIdx.y;              // 0..511
    int tid = threadIdx.x;
    int wid = tid >> 5, lane = tid & 31;
    int wm = wid & 3, wn = wid >> 2;  // warp tile: rows wm*32, cols wn*64
    int g = lane >> 2, t4 = lane & 3;

    // per-thread LDSM address components (bytes, relative to stage base)
    uint32_t aBase = (uint32_t)(((wm * 32 + (lane & 15)) * SA + (lane >> 4) * 8) * 2);
    uint32_t bBase = (uint32_t)(((wn * 64 + (lane & 7) + ((lane >> 4) << 3)) * SA
                                 + ((lane >> 3) & 1) * 8) * 2);

    int r0v = tid >> 3;               // rows step 32 per j
    int cv  = (tid & 7) * 8;          // col elems

    float acc[2][8][4];
    #pragma unroll
    for (int mt = 0; mt < 2; mt++)
        #pragma unroll
        for (int nt = 0; nt < 8; nt++)
            #pragma unroll
            for (int i = 0; i < 4; i++) acc[mt][nt][i] = 0.f;

    auto load_stage = [&](int kc, int st) {
        uint32_t aDst = smem_u32 + (uint32_t)(st * A_STG * 2);
        uint32_t wDst = smem_u32 + (uint32_t)((W_BASE + st * W_STG) * 2);
        #pragma unroll
        for (int j = 0; j < 4; j++) {
            int r = r0v + j * 32;
            cp_async16(aDst + (uint32_t)((r * SA + cv) * 2),
                       &g_A[(size_t)(bm * BM + r) * KK + kc * KC + cv]);
            cp_async16(wDst + (uint32_t)((r * SA + cv) * 2),
                       &g_W[(size_t)(bn * BN + r) * KK + kc * KC + cv]);
        }
    };

    load_stage(0, 0);
    asm volatile("cp.async.commit_group;\n");
    load_stage(1, 1);
    asm volatile("cp.async.commit_group;\n");

    for (int kc = 0; kc < KK / KC; kc++) {
        asm volatile("cp.async.wait_group 1;\n");   // stage kc resident
        __syncthreads();
        if (kc + 2 < KK / KC) load_stage(kc + 2, (kc + 2) % NST);
        asm volatile("cp.async.commit_group;\n");   // always commit (group counting)

        int st = kc % NST;
        uint32_t aStage = smem_u32 + (uint32_t)(st * A_STG * 2) + aBase;
        uint32_t wStage = smem_u32 + (uint32_t)((W_BASE + st * W_STG) * 2) + bBase;

        #pragma unroll
        for (int s = 0; s < KC / 16; s++) {
            int kb = s * 16;
            uint32_t af[2][4], bfr[8][2];
            #pragma unroll
            for (int mt = 0; mt < 2; mt++)
                ldsm4(af[mt][0], af[mt][1], af[mt][2], af[mt][3],
                      aStage + (uint32_t)((mt * 16 * SA + kb) * 2));
            #pragma unroll
            for (int p = 0; p < 4; p++)
                ldsm4(bfr[2 * p][0], bfr[2 * p][1], bfr[2 * p + 1][0], bfr[2 * p + 1][1],
                      wStage + (uint32_t)((p * 16 * SA + kb) * 2));
            #pragma unroll
            for (int mt = 0; mt < 2; mt++)
                #pragma unroll
                for (int nt = 0; nt < 8; nt++)
                    mma16816(acc[mt][nt], af[mt], bfr[nt]);
        }
        // stage st only overwritten by the load issued AFTER the next
        // iteration's __syncthreads -> no trailing sync needed
    }

    // epilogue: add cterm, store fp16 scores, write per-(row, 64col) block max
    int n0 = bn * BN + wn * 64;
    float rmax[2][2] = {{NEG_INF, NEG_INF}, {NEG_INF, NEG_INF}};
    #pragma unroll
    for (int mt = 0; mt < 2; mt++) {
        int row0 = bm * BM + wm * 32 + mt * 16 + g;
        #pragma unroll
        for (int nt = 0; nt < 8; nt++) {
            int col = n0 + nt * 8 + t4 * 2;
            float2 ct = *(const float2*)&g_cterm[col];
            float v0 = acc[mt][nt][0] + ct.x;
            float v1 = acc[mt][nt][1] + ct.y;
            float v2 = acc[mt][nt][2] + ct.x;
            float v3 = acc[mt][nt][3] + ct.y;
            *(__half2*)&g_S[(size_t)row0 * KCL + col]       = __floats2half2_rn(v0, v1);
            *(__half2*)&g_S[(size_t)(row0 + 8) * KCL + col] = __floats2half2_rn(v2, v3);
            rmax[mt][0] = fmaxf(rmax[mt][0], fmaxf(v0, v1));
            rmax[mt][1] = fmaxf(rmax[mt][1], fmaxf(v2, v3));
        }
    }
    int blk = bn * 2 + wn;
    #pragma unroll
    for (int mt = 0; mt < 2; mt++)
        #pragma unroll
        for (int h = 0; h < 2; h++) {
            float v = rmax[mt][h];
            v = fmaxf(v, __shfl_xor_sync(0xffffffffu, v, 1));
            v = fmaxf(v, __shfl_xor_sync(0xffffffffu, v, 2));
            if (t4 == 0) {
                int row = bm * BM + wm * 32 + mt * 16 + h * 8 + g;
                g_blk[(size_t)row * NBLK + blk] = v;   // unique writer per (row, blk)
            }
        }
}

// ---------------- candidate selection via block-max order statistics ------
// Block maxima are a subset of the scores, so the 32nd-largest block max
// theta_b <= 32nd-largest score, and >=32 blocks above theta_b imply >=32 fp16
// scores >= theta_b - 0.125. Hence lp32_true >= theta_b - 0.125 - err and every
// true top-32 member has fp16 score >= theta_b - 0.125 - 2*err. With err<=1.5
// (bf16 gemm + fp16 store), collecting at Tc = theta_b - 3.25 is inclusive.
// theta_b located by a histogram of the 1024 block maxima + parallel prefix.
__global__ __launch_bounds__(256) void select_kernel() {
    int b = blockIdx.x;
    int tid = threadIdx.x, wid = tid >> 5, lane = tid & 31;
    __shared__ float blk[NBLK];
    __shared__ unsigned hist[2048];
    __shared__ float smax[8];
    __shared__ unsigned wsum[8];
    __shared__ int s_bin;
    __shared__ int s_cnt;

    for (int i = tid; i < NBLK; i += 256) blk[i] = g_blk[(size_t)b * NBLK + i];
    for (int i = tid; i < 2048; i += 256) hist[i] = 0u;
    if (tid == 0) { s_cnt = 0; s_bin = 2047; }
    __syncthreads();

    // row max over block maxima
    float m = NEG_INF;
    for (int i = tid; i < NBLK; i += 256) m = fmaxf(m, blk[i]);
    #pragma unroll
    for (int o = 16; o; o >>= 1) m = fmaxf(m, __shfl_xor_sync(0xffffffffu, m, o));
    if (lane == 0) smax[wid] = m;
    __syncthreads();
    float M = fmaxf(fmaxf(fmaxf(smax[0], smax[1]), fmaxf(smax[2], smax[3])),
                    fmaxf(fmaxf(smax[4], smax[5]), fmaxf(smax[6], smax[7])));

    // histogram of (M - blkmax), 0.125-wide bins, clamped to 2047
    for (int i = tid; i < NBLK; i += 256) {
        float d = M - blk[i];
        int bin = (int)(d * 8.0f);
        atomicAdd(&hist[min(bin, 2047)], 1u);
    }
    __syncthreads();

    // parallel search for first bin with cumulative >= TOPK
    unsigned seg = 0;
    #pragma unroll
    for (int j = 0; j < 8; j++) seg += hist[tid * 8 + j];
    unsigned inc = seg;
    #pragma unroll
    for (int o = 1; o < 32; o <<= 1) {
        unsigned n = __shfl_up_sync(0xffffffffu, inc, o);
        if (lane >= o) inc += n;
    }
    if (lane == 31) wsum[wid] = inc;
    __syncthreads();
    unsigned woff = 0;
    for (int q = 0; q < wid; q++) woff += wsum[q];
    unsigned incl = inc + woff;
    unsigned excl = incl - seg;
    if (excl < TOPK && incl >= TOPK) {   // unique crossing segment
        unsigned cum = excl;
        #pragma unroll
        for (int j = 0; j < 8; j++) {
            cum += hist[tid * 8 + j];
            if (cum >= TOPK) { s_bin = tid * 8 + j; break; }
        }
    }
    __syncthreads();

    // theta_b lower bound; inclusive collection threshold
    float theta = M - (float)(s_bin + 1) * 0.125f;
    float Tc = theta - 3.25f;           // 0.125 fp16 subset + 2*1.5 err margin
    float Tb = Tc - 0.25f;              // fp32 blkmax vs fp16 score slack

    for (int j = wid; j < NBLK; j += 8) {        // j uniform per warp
        if (blk[j] < Tb) continue;
        const __half2* p2 = (const __half2*)&g_S[(size_t)b * KCL + j * 64];
        float2 f = __half22float2(p2[lane]);
        int col = j * 64 + lane * 2;
        if (f.x >= Tc) {
            int p = atomicAdd(&s_cnt, 1);
            if (p < CAND_CAP) g_cand[(size_t)b * CAND_CAP + p] = col;
        }
        if (f.y >= Tc) {
            int p = atomicAdd(&s_cnt, 1);
            if (p < CAND_CAP) g_cand[(size_t)b * CAND_CAP + p] = col + 1;
        }
    }
    __syncthreads();
    if (tid == 0) g_cnt[b] = min(s_cnt, CAND_CAP);
}

// ---------------- exact rescore + top-32 (rank count) + softmax + gather --
__global__ __launch_bounds__(256) void rescore_kernel(const float* __restrict__ x,
                                                      const float* __restrict__ mean,
                                                      const float* __restrict__ stddev,
                                                      const float* __restrict__ outputs,
                                                      float* __restrict__ out) {
    int b = blockIdx.x;
    int tid = threadIdx.x, wid = tid >> 5, lane = tid & 31;
    __shared__ float xs[DD];
    __shared__ float lp_s[CAND_CAP];
    __shared__ int   ck[CAND_CAP];
    __shared__ int   selk[TOPK];
    __shared__ float selw[TOPK];

    xs[tid] = x[b * DD + tid];
    int cnt = g_cnt[b];
    __syncthreads();

    // exact fp32 log-prob for each candidate (one warp per candidate)
    for (int j = wid; j < cnt; j += 8) {
        int k = g_cand[(size_t)b * CAND_CAP + j];
        float acc = 0.f;
        #pragma unroll
        for (int t = 0; t < 8; t++) {
            int d = lane + t * 32;
            float mu = mean[k * DD + d];
            float sg = stddev[k * DD + d];
            float iv = 1.0f / (sg * sg);
            float df = xs[d] - mu;
            acc += df * df * iv;
        }
        #pragma unroll
        for (int o = 16; o; o >>= 1) acc += __shfl_xor_sync(0xffffffffu, acc, o);
        if (lane == 0) {
            lp_s[j] = -0.5f * acc - g_logn[k] - 128.0f * LOG2PI;
            ck[j] = k;
        }
    }
    __syncthreads();

    // top-32 by rank counting (deterministic: ties broken by cluster id)
    for (int i = tid; i < cnt; i += 256) {
        float v = lp_s[i];
        int ki = ck[i];
        int rank = 0;
        for (int j = 0; j < cnt; j++) {
            float u = lp_s[j];
            rank += (u > v) || (u == v && ck[j] < ki);
            if (rank >= TOPK) break;
        }
        if (rank < TOPK) { selk[rank] = ki; selw[rank] = v; }
    }
    __syncthreads();

    // softmax over the 32 (rank 0 holds the max)
    if (tid == 0) {
        float m = selw[0], z = 0.f;
        #pragma unroll
        for (int i = 0; i < TOPK; i++) { float e = expf(selw[i] - m); selw[i] = e; z += e; }
        float iz = 1.0f / z;
        #pragma unroll
        for (int i = 0; i < TOPK; i++) selw[i] *= iz;
    }
    __syncthreads();

    // weighted gather: out[b, o] = sum_i w_i * outputs[k_i, o]
    float acc = 0.f;
    #pragma unroll 8
    for (int i = 0; i < TOPK; i++)
        acc += selw[i] * outputs[selk[i] * OO + tid];
    out[b * OO + tid] = acc;
}

// ---------------- launch -----------------------------------------------
extern "C" void kernel_launch(void* const* d_in, const int* in_sizes, int n_in,
                              void* d_out, int out_size) {
    const float* x       = (const float*)d_in[0];
    const float* mean    = (const float*)d_in[1];
    const float* stddev  = (const float*)d_in[2];
    const float* outputs = (const float*)d_in[3];
    float* out = (float*)d_out;
    (void)in_sizes; (void)n_in; (void)out_size;

    cudaFuncSetAttribute(gemm_kernel, cudaFuncAttributeMaxDynamicSharedMemorySize, SMEM_BYTES);

    prep_x_kernel<<<BB, 256>>>(x);
    prep_w_kernel<<<KCL, 256>>>(mean, stddev);
    gemm_kernel<<<dim3(BB / BM, KCL / BN), 256, SMEM_BYTES>>>();
    select_kernel<<<BB, 256>>>();
    rescore_kernel<<<BB, 256>>>(x, mean, stddev, outputs, out);
}

// round 11
// speedup vs baseline: 1.2900x; 1.0887x over previous
#include <cuda_runtime.h>
#include <cuda_bf16.h>
#include <cuda_fp16.h>
#include <cstdint>

// Problem constants (fixed by setup_inputs)
#define KCL 65536      // number of clusters (GEMM N)
#define DD  256        // feature dim
#define OO  256        // output dim
#define BB  1024       // batch rows (GEMM M)
#define TOPK 32
#define KK  512        // GEMM reduction dim (2*DD)
#define CAND_CAP 2048
#define NBLK (KCL / 64)    // 1024 score-blocks of 64 cols per row

// ---------------- scratch (static device globals; no allocations) ----------
__device__ __nv_bfloat16 g_W[(size_t)KCL * KK];          // 64 MB
__device__ __nv_bfloat16 g_A[(size_t)BB * KK];           // 1 MB
__device__ float g_cterm[KCL];
__device__ float g_logn[KCL];
__device__ __half g_S[(size_t)BB * KCL];                 // 128 MB fp16 scores
__device__ float g_blk[(size_t)BB * NBLK];               // 4 MB per-64col block maxima
__device__ int g_cand[(size_t)BB * CAND_CAP];
__device__ int g_cnt[BB];

#define NEG_INF (__int_as_float(0xff800000))
#define LOG2PI 1.8378770664093455f

// ---------------- prep A = [x*x, x] (bf16) ------------------------------
__global__ void prep_x_kernel(const float* __restrict__ x) {
    int b = blockIdx.x;
    int d = threadIdx.x;
    float v = x[b * DD + d];
    g_A[b * KK + d]      = __float2bfloat16(v * v);
    g_A[b * KK + DD + d] = __float2bfloat16(v);
}

// ---------------- prep W: one warp per cluster, 8 clusters per block ------
__global__ __launch_bounds__(256) void prep_w_kernel(const float* __restrict__ mean,
                                                     const float* __restrict__ stddev) {
    int k = blockIdx.x * 8 + (threadIdx.x >> 5);
    int lane = threadIdx.x & 31;
    const float* mp = &mean[(size_t)k * DD];
    const float* sp = &stddev[(size_t)k * DD];
    __nv_bfloat16* w0 = &g_W[(size_t)k * KK];

    float s1 = 0.f, s2 = 0.f;
    #pragma unroll
    for (int t = 0; t < 8; t++) {
        int d = lane + t * 32;
        float mu = mp[d];
        float sg = sp[d];
        float iv = __fdividef(1.0f, sg * sg);
        w0[d]      = __float2bfloat16(-0.5f * iv);
        w0[DD + d] = __float2bfloat16(mu * iv);
        s1 += mu * mu * iv;
        s2 += __logf(sg);
    }
    #pragma unroll
    for (int o = 16; o; o >>= 1) {
        s1 += __shfl_xor_sync(0xffffffffu, s1, o);
        s2 += __shfl_xor_sync(0xffffffffu, s2, o);
    }
    if (lane == 0) {
        g_logn[k]  = s2;
        g_cterm[k] = -0.5f * s1 - s2 - 128.0f * LOG2PI;
    }
}

// ---------------- bf16 mma GEMM: S = A @ W^T + cterm --------------------
// 8 warps/CTA, 32x64 warp tiles, 2 CTAs/SM, 3-stage cp.async pipeline,
// register-level double buffering of ldmatrix fragments (overlap LDSM of
// step s+1 with the MMAs of step s).
#define BM 128
#define BN 128
#define KC 64
#define NST 3
#define SA 72   // padded smem stride (elems); conflict-free ldmatrix

#define A_STG (BM * SA)                 // elems per A stage
#define W_STG (BN * SA)
#define W_BASE (NST * A_STG)            // layout: [A0][A1][A2][W0][W1][W2]
#define SMEM_BYTES ((NST * A_STG + NST * W_STG) * 2)   // 110,592 B -> 2 CTAs/SM

__device__ __forceinline__ void mma16816(float* c, const uint32_t* a, const uint32_t* b) {
    asm volatile(
        "mma.sync.aligned.m16n8k16.row.col.f32.bf16.bf16.f32 "
        "{%0,%1,%2,%3}, {%4,%5,%6,%7}, {%8,%9}, {%0,%1,%2,%3};\n"
        : "+f"(c[0]), "+f"(c[1]), "+f"(c[2]), "+f"(c[3])
        : "r"(a[0]), "r"(a[1]), "r"(a[2]), "r"(a[3]), "r"(b[0]), "r"(b[1]));
}

__device__ __forceinline__ void ldsm4(uint32_t& r0, uint32_t& r1, uint32_t& r2, uint32_t& r3,
                                      uint32_t addr) {
    asm volatile("ldmatrix.sync.aligned.m8n8.x4.shared.b16 {%0,%1,%2,%3}, [%4];\n"
                 : "=r"(r0), "=r"(r1), "=r"(r2), "=r"(r3) : "r"(addr));
}

__device__ __forceinline__ void cp_async16(uint32_t smem_dst, const void* gmem_src) {
    asm volatile("cp.async.cg.shared.global [%0], [%1], 16;\n" :: "r"(smem_dst), "l"(gmem_src));
}

__global__ __launch_bounds__(256, 2) void gemm_kernel() {
    extern __shared__ __nv_bfloat16 sh[];
    uint32_t smem_u32 = (uint32_t)__cvta_generic_to_shared(sh);

    int bm = blockIdx.x;              // 0..7   (fast dim -> W tile reused across bm in L2)
    int bn = blockIdx.y;              // 0..511
    int tid = threadIdx.x;
    int wid = tid >> 5, lane = tid & 31;
    int wm = wid & 3, wn = wid >> 2;  // warp tile: rows wm*32, cols wn*64
    int g = lane >> 2, t4 = lane & 3;

    // per-thread LDSM address components (bytes, relative to stage base)
    uint32_t aBase = (uint32_t)(((wm * 32 + (lane & 15)) * SA + (lane >> 4) * 8) * 2);
    uint32_t bBase = (uint32_t)(((wn * 64 + (lane & 7) + ((lane >> 4) << 3)) * SA
                                 + ((lane >> 3) & 1) * 8) * 2);

    int r0v = tid >> 3;               // rows step 32 per j
    int cv  = (tid & 7) * 8;          // col elems

    float acc[2][8][4];
    #pragma unroll
    for (int mt = 0; mt < 2; mt++)
        #pragma unroll
        for (int nt = 0; nt < 8; nt++)
            #pragma unroll
            for (int i = 0; i < 4; i++) acc[mt][nt][i] = 0.f;

    auto load_stage = [&](int kc, int st) {
        uint32_t aDst = smem_u32 + (uint32_t)(st * A_STG * 2);
        uint32_t wDst = smem_u32 + (uint32_t)((W_BASE + st * W_STG) * 2);
        #pragma unroll
        for (int j = 0; j < 4; j++) {
            int r = r0v + j * 32;
            cp_async16(aDst + (uint32_t)((r * SA + cv) * 2),
                       &g_A[(size_t)(bm * BM + r) * KK + kc * KC + cv]);
            cp_async16(wDst + (uint32_t)((r * SA + cv) * 2),
                       &g_W[(size_t)(bn * BN + r) * KK + kc * KC + cv]);
        }
    };

    load_stage(0, 0);
    asm volatile("cp.async.commit_group;\n");
    load_stage(1, 1);
    asm volatile("cp.async.commit_group;\n");

    uint32_t af[2][2][4], bfr[2][8][2];   // double-buffered fragments

    for (int kc = 0; kc < KK / KC; kc++) {
        asm volatile("cp.async.wait_group 1;\n");   // stage kc resident
        __syncthreads();
        if (kc + 2 < KK / KC) load_stage(kc + 2, (kc + 2) % NST);
        asm volatile("cp.async.commit_group;\n");   // always commit (group counting)

        int st = kc % NST;
        uint32_t aStage = smem_u32 + (uint32_t)(st * A_STG * 2) + aBase;
        uint32_t wStage = smem_u32 + (uint32_t)((W_BASE + st * W_STG) * 2) + bBase;

        // preload fragments for step 0
        #pragma unroll
        for (int mt = 0; mt < 2; mt++)
            ldsm4(af[0][mt][0], af[0][mt][1], af[0][mt][2], af[0][mt][3],
                  aStage + (uint32_t)((mt * 16 * SA) * 2));
        #pragma unroll
        for (int p = 0; p < 4; p++)
            ldsm4(bfr[0][2 * p][0], bfr[0][2 * p][1], bfr[0][2 * p + 1][0], bfr[0][2 * p + 1][1],
                  wStage + (uint32_t)((p * 16 * SA) * 2));

        #pragma unroll
        for (int s = 0; s < KC / 16; s++) {
            int cur = s & 1, nxt = cur ^ 1;
            if (s + 1 < KC / 16) {       // prefetch next step's fragments
                int kb = (s + 1) * 16;
                #pragma unroll
                for (int mt = 0; mt < 2; mt++)
                    ldsm4(af[nxt][mt][0], af[nxt][mt][1], af[nxt][mt][2], af[nxt][mt][3],
                          aStage + (uint32_t)((mt * 16 * SA + kb) * 2));
                #pragma unroll
                for (int p = 0; p < 4; p++)
                    ldsm4(bfr[nxt][2 * p][0], bfr[nxt][2 * p][1],
                          bfr[nxt][2 * p + 1][0], bfr[nxt][2 * p + 1][1],
                          wStage + (uint32_t)((p * 16 * SA + kb) * 2));
            }
            #pragma unroll
            for (int mt = 0; mt < 2; mt++)
                #pragma unroll
                for (int nt = 0; nt < 8; nt++)
                    mma16816(acc[mt][nt], af[cur][mt], bfr[cur][nt]);
        }
        // stage st only overwritten by the load issued AFTER the next
        // iteration's __syncthreads -> no trailing sync needed
    }

    // epilogue: add cterm, store fp16 scores, write per-(row, 64col) block max
    int n0 = bn * BN + wn * 64;
    float rmax[2][2] = {{NEG_INF, NEG_INF}, {NEG_INF, NEG_INF}};
    #pragma unroll
    for (int mt = 0; mt < 2; mt++) {
        int row0 = bm * BM + wm * 32 + mt * 16 + g;
        #pragma unroll
        for (int nt = 0; nt < 8; nt++) {
            int col = n0 + nt * 8 + t4 * 2;
            float2 ct = *(const float2*)&g_cterm[col];
            float v0 = acc[mt][nt][0] + ct.x;
            float v1 = acc[mt][nt][1] + ct.y;
            float v2 = acc[mt][nt][2] + ct.x;
            float v3 = acc[mt][nt][3] + ct.y;
            *(__half2*)&g_S[(size_t)row0 * KCL + col]       = __floats2half2_rn(v0, v1);
            *(__half2*)&g_S[(size_t)(row0 + 8) * KCL + col] = __floats2half2_rn(v2, v3);
            rmax[mt][0] = fmaxf(rmax[mt][0], fmaxf(v0, v1));
            rmax[mt][1] = fmaxf(rmax[mt][1], fmaxf(v2, v3));
        }
    }
    int blk = bn * 2 + wn;
    #pragma unroll
    for (int mt = 0; mt < 2; mt++)
        #pragma unroll
        for (int h = 0; h < 2; h++) {
            float v = rmax[mt][h];
            v = fmaxf(v, __shfl_xor_sync(0xffffffffu, v, 1));
            v = fmaxf(v, __shfl_xor_sync(0xffffffffu, v, 2));
            if (t4 == 0) {
                int row = bm * BM + wm * 32 + mt * 16 + h * 8 + g;
                g_blk[(size_t)row * NBLK + blk] = v;   // unique writer per (row, blk)
            }
        }
}

// ---------------- candidate selection via block-max order statistics ------
// Block maxima are a subset of the scores, so the 32nd-largest block max
// theta_b <= 32nd-largest score, and >=32 blocks above theta_b imply >=32 fp16
// scores >= theta_b - 0.125. Hence lp32_true >= theta_b - 0.125 - err and every
// true top-32 member has fp16 score >= theta_b - 0.125 - 2*err. With err<=1.5
// (bf16 gemm + fp16 store), collecting at Tc = theta_b - 3.25 is inclusive.
__global__ __launch_bounds__(256) void select_kernel() {
    int b = blockIdx.x;
    int tid = threadIdx.x, wid = tid >> 5, lane = tid & 31;
    __shared__ float blk[NBLK];
    __shared__ unsigned hist[2048];
    __shared__ float smax[8];
    __shared__ unsigned wsum[8];
    __shared__ int s_bin;
    __shared__ int s_cnt;

    for (int i = tid; i < NBLK; i += 256) blk[i] = g_blk[(size_t)b * NBLK + i];
    for (int i = tid; i < 2048; i += 256) hist[i] = 0u;
    if (tid == 0) { s_cnt = 0; s_bin = 2047; }
    __syncthreads();

    // row max over block maxima
    float m = NEG_INF;
    for (int i = tid; i < NBLK; i += 256) m = fmaxf(m, blk[i]);
    #pragma unroll
    for (int o = 16; o; o >>= 1) m = fmaxf(m, __shfl_xor_sync(0xffffffffu, m, o));
    if (lane == 0) smax[wid] = m;
    __syncthreads();
    float M = fmaxf(fmaxf(fmaxf(smax[0], smax[1]), fmaxf(smax[2], smax[3])),
                    fmaxf(fmaxf(smax[4], smax[5]), fmaxf(smax[6], smax[7])));

    // histogram of (M - blkmax), 0.125-wide bins, clamped to 2047
    for (int i = tid; i < NBLK; i += 256) {
        float d = M - blk[i];
        int bin = (int)(d * 8.0f);
        atomicAdd(&hist[min(bin, 2047)], 1u);
    }
    __syncthreads();

    // parallel search for first bin with cumulative >= TOPK
    unsigned seg = 0;
    #pragma unroll
    for (int j = 0; j < 8; j++) seg += hist[tid * 8 + j];
    unsigned inc = seg;
    #pragma unroll
    for (int o = 1; o < 32; o <<= 1) {
        unsigned n = __shfl_up_sync(0xffffffffu, inc, o);
        if (lane >= o) inc += n;
    }
    if (lane == 31) wsum[wid] = inc;
    __syncthreads();
    unsigned woff = 0;
    for (int q = 0; q < wid; q++) woff += wsum[q];
    unsigned incl = inc + woff;
    unsigned excl = incl - seg;
    if (excl < TOPK && incl >= TOPK) {   // unique crossing segment
        unsigned cum = excl;
        #pragma unroll
        for (int j = 0; j < 8; j++) {
            cum += hist[tid * 8 + j];
            if (cum >= TOPK) { s_bin = tid * 8 + j; break; }
        }
    }
    __syncthreads();

    // theta_b lower bound; inclusive collection threshold
    float theta = M - (float)(s_bin + 1) * 0.125f;
    float Tc = theta - 3.25f;           // 0.125 fp16 subset + 2*1.5 err margin
    float Tb = Tc - 0.25f;              // fp32 blkmax vs fp16 score slack

    for (int j = wid; j < NBLK; j += 8) {        // j uniform per warp
        if (blk[j] < Tb) continue;
        const __half2* p2 = (const __half2*)&g_S[(size_t)b * KCL + j * 64];
        float2 f = __half22float2(p2[lane]);
        int col = j * 64 + lane * 2;
        if (f.x >= Tc) {
            int p = atomicAdd(&s_cnt, 1);
            if (p < CAND_CAP) g_cand[(size_t)b * CAND_CAP + p] = col;
        }
        if (f.y >= Tc) {
            int p = atomicAdd(&s_cnt, 1);
            if (p < CAND_CAP) g_cand[(size_t)b * CAND_CAP + p] = col + 1;
        }
    }
    __syncthreads();
    if (tid == 0) g_cnt[b] = min(s_cnt, CAND_CAP);
}

// ---------------- exact rescore + top-32 (rank count) + softmax + gather --
__global__ __launch_bounds__(256) void rescore_kernel(const float* __restrict__ x,
                                                      const float* __restrict__ mean,
                                                      const float* __restrict__ stddev,
                                                      const float* __restrict__ outputs,
                                                      float* __restrict__ out) {
    int b = blockIdx.x;
    int tid = threadIdx.x, wid = tid >> 5, lane = tid & 31;
    __shared__ float xs[DD];
    __shared__ float lp_s[CAND_CAP];
    __shared__ int   ck[CAND_CAP];
    __shared__ int   selk[TOPK];
    __shared__ float selw[TOPK];

    xs[tid] = x[b * DD + tid];
    int cnt = g_cnt[b];
    __syncthreads();

    // exact fp32 log-prob for each candidate (one warp per candidate)
    for (int j = wid; j < cnt; j += 8) {
        int k = g_cand[(size_t)b * CAND_CAP + j];
        float acc = 0.f;
        #pragma unroll
        for (int t = 0; t < 8; t++) {
            int d = lane + t * 32;
            float mu = mean[k * DD + d];
            float sg = stddev[k * DD + d];
            float iv = 1.0f / (sg * sg);
            float df = xs[d] - mu;
            acc += df * df * iv;
        }
        #pragma unroll
        for (int o = 16; o; o >>= 1) acc += __shfl_xor_sync(0xffffffffu, acc, o);
        if (lane == 0) {
            lp_s[j] = -0.5f * acc - g_logn[k] - 128.0f * LOG2PI;
            ck[j] = k;
        }
    }
    __syncthreads();

    // top-32 by rank counting (deterministic: ties broken by cluster id)
    for (int i = tid; i < cnt; i += 256) {
        float v = lp_s[i];
        int ki = ck[i];
        int rank = 0;
        for (int j = 0; j < cnt; j++) {
            float u = lp_s[j];
            rank += (u > v) || (u == v && ck[j] < ki);
            if (rank >= TOPK) break;
        }
        if (rank < TOPK) { selk[rank] = ki; selw[rank] = v; }
    }
    __syncthreads();

    // softmax over the 32 (rank 0 holds the max)
    if (tid == 0) {
        float m = selw[0], z = 0.f;
        #pragma unroll
        for (int i = 0; i < TOPK; i++) { float e = expf(selw[i] - m); selw[i] = e; z += e; }
        float iz = 1.0f / z;
        #pragma unroll
        for (int i = 0; i < TOPK; i++) selw[i] *= iz;
    }
    __syncthreads();

    // weighted gather: out[b, o] = sum_i w_i * outputs[k_i, o]
    float acc = 0.f;
    #pragma unroll 8
    for (int i = 0; i < TOPK; i++)
        acc += selw[i] * outputs[selk[i] * OO + tid];
    out[b * OO + tid] = acc;
}

// ---------------- launch -----------------------------------------------
extern "C" void kernel_launch(void* const* d_in, const int* in_sizes, int n_in,
                              void* d_out, int out_size) {
    const float* x       = (const float*)d_in[0];
    const float* mean    = (const float*)d_in[1];
    const float* stddev  = (const float*)d_in[2];
    const float* outputs = (const float*)d_in[3];
    float* out = (float*)d_out;
    (void)in_sizes; (void)n_in; (void)out_size;

    cudaFuncSetAttribute(gemm_kernel, cudaFuncAttributeMaxDynamicSharedMemorySize, SMEM_BYTES);

    prep_x_kernel<<<BB, 256>>>(x);
    prep_w_kernel<<<KCL / 8, 256>>>(mean, stddev);
    gemm_kernel<<<dim3(BB / BM, KCL / BN), 256, SMEM_BYTES>>>();
    select_kernel<<<BB, 256>>>();
    rescore_kernel<<<BB, 256>>>(x, mean, stddev, outputs, out);
}

// round 12
// speedup vs baseline: 1.4193x; 1.1003x over previous
#include <cuda_runtime.h>
#include <cuda_bf16.h>
#include <cuda_fp16.h>
#include <cstdint>

// Problem constants (fixed by setup_inputs)
#define KCL 65536      // number of clusters (GEMM N)
#define DD  256        // feature dim
#define OO  256        // output dim
#define BB  1024       // batch rows (GEMM M)
#define TOPK 32
#define KK  512        // GEMM reduction dim (2*DD)
#define CAND_CAP 2048
#define NBLK (KCL / 64)    // 1024 score-blocks of 64 cols per row

// ---------------- scratch (static device globals; no allocations) ----------
__device__ __nv_bfloat16 g_W[(size_t)KCL * KK];          // 64 MB
__device__ __nv_bfloat16 g_A[(size_t)BB * KK];           // 1 MB
__device__ float g_cterm[KCL];
__device__ float g_logn[KCL];
__device__ __half g_S[(size_t)BB * KCL];                 // 128 MB fp16 scores
__device__ float g_blk[(size_t)BB * NBLK];               // 4 MB per-64col block maxima
__device__ int g_cand[(size_t)BB * CAND_CAP];
__device__ float g_lpbuf[(size_t)BB * CAND_CAP];         // 8 MB exact lp per candidate
__device__ int g_cnt[BB];
__device__ int g_pref[BB + 1];

#define NEG_INF (__int_as_float(0xff800000))
#define LOG2PI 1.8378770664093455f

// ---------------- prep A = [x*x, x] (bf16) ------------------------------
__global__ void prep_x_kernel(const float* __restrict__ x) {
    int b = blockIdx.x;
    int d = threadIdx.x;
    float v = x[b * DD + d];
    g_A[b * KK + d]      = __float2bfloat16(v * v);
    g_A[b * KK + DD + d] = __float2bfloat16(v);
}

// ---------------- prep W: one warp per cluster, 8 clusters per block ------
__global__ __launch_bounds__(256) void prep_w_kernel(const float* __restrict__ mean,
                                                     const float* __restrict__ stddev) {
    int k = blockIdx.x * 8 + (threadIdx.x >> 5);
    int lane = threadIdx.x & 31;
    const float* mp = &mean[(size_t)k * DD];
    const float* sp = &stddev[(size_t)k * DD];
    __nv_bfloat16* w0 = &g_W[(size_t)k * KK];

    float s1 = 0.f, s2 = 0.f;
    #pragma unroll
    for (int t = 0; t < 8; t++) {
        int d = lane + t * 32;
        float mu = mp[d];
        float sg = sp[d];
        float iv = __fdividef(1.0f, sg * sg);
        w0[d]      = __float2bfloat16(-0.5f * iv);
        w0[DD + d] = __float2bfloat16(mu * iv);
        s1 += mu * mu * iv;
        s2 += __logf(sg);
    }
    #pragma unroll
    for (int o = 16; o; o >>= 1) {
        s1 += __shfl_xor_sync(0xffffffffu, s1, o);
        s2 += __shfl_xor_sync(0xffffffffu, s2, o);
    }
    if (lane == 0) {
        g_logn[k]  = s2;
        g_cterm[k] = -0.5f * s1 - s2 - 128.0f * LOG2PI;
    }
}

// ---------------- bf16 mma GEMM: S = A @ W^T + cterm --------------------
#define BM 128
#define BN 128
#define KC 64
#define NST 3
#define SA 72   // padded smem stride (elems); conflict-free ldmatrix

#define A_STG (BM * SA)                 // elems per A stage
#define W_STG (BN * SA)
#define W_BASE (NST * A_STG)            // layout: [A0][A1][A2][W0][W1][W2]
#define SMEM_BYTES ((NST * A_STG + NST * W_STG) * 2)   // 110,592 B -> 2 CTAs/SM

__device__ __forceinline__ void mma16816(float* c, const uint32_t* a, const uint32_t* b) {
    asm volatile(
        "mma.sync.aligned.m16n8k16.row.col.f32.bf16.bf16.f32 "
        "{%0,%1,%2,%3}, {%4,%5,%6,%7}, {%8,%9}, {%0,%1,%2,%3};\n"
        : "+f"(c[0]), "+f"(c[1]), "+f"(c[2]), "+f"(c[3])
        : "r"(a[0]), "r"(a[1]), "r"(a[2]), "r"(a[3]), "r"(b[0]), "r"(b[1]));
}

__device__ __forceinline__ void ldsm4(uint32_t& r0, uint32_t& r1, uint32_t& r2, uint32_t& r3,
                                      uint32_t addr) {
    asm volatile("ldmatrix.sync.aligned.m8n8.x4.shared.b16 {%0,%1,%2,%3}, [%4];\n"
                 : "=r"(r0), "=r"(r1), "=r"(r2), "=r"(r3) : "r"(addr));
}

__device__ __forceinline__ void cp_async16(uint32_t smem_dst, const void* gmem_src) {
    asm volatile("cp.async.cg.shared.global [%0], [%1], 16;\n" :: "r"(smem_dst), "l"(gmem_src));
}

__global__ __launch_bounds__(256, 2) void gemm_kernel() {
    extern __shared__ __nv_bfloat16 sh[];
    uint32_t smem_u32 = (uint32_t)__cvta_generic_to_shared(sh);

    int bm = blockIdx.x;              // 0..7   (fast dim -> W tile reused across bm in L2)
    int bn = blockIdx.y;              // 0..511
    int tid = threadIdx.x;
    int wid = tid >> 5, lane = tid & 31;
    int wm = wid & 3, wn = wid >> 2;  // warp tile: rows wm*32, cols wn*64
    int g = lane >> 2, t4 = lane & 3;

    // per-thread LDSM address components (bytes, relative to stage base)
    uint32_t aBase = (uint32_t)(((wm * 32 + (lane & 15)) * SA + (lane >> 4) * 8) * 2);
    uint32_t bBase = (uint32_t)(((wn * 64 + (lane & 7) + ((lane >> 4) << 3)) * SA
                                 + ((lane >> 3) & 1) * 8) * 2);

    int r0v = tid >> 3;               // rows step 32 per j
    int cv  = (tid & 7) * 8;          // col elems

    float acc[2][8][4];
    #pragma unroll
    for (int mt = 0; mt < 2; mt++)
        #pragma unroll
        for (int nt = 0; nt < 8; nt++)
            #pragma unroll
            for (int i = 0; i < 4; i++) acc[mt][nt][i] = 0.f;

    auto load_stage = [&](int kc, int st) {
        uint32_t aDst = smem_u32 + (uint32_t)(st * A_STG * 2);
        uint32_t wDst = smem_u32 + (uint32_t)((W_BASE + st * W_STG) * 2);
        #pragma unroll
        for (int j = 0; j < 4; j++) {
            int r = r0v + j * 32;
            cp_async16(aDst + (uint32_t)((r * SA + cv) * 2),
                       &g_A[(size_t)(bm * BM + r) * KK + kc * KC + cv]);
            cp_async16(wDst + (uint32_t)((r * SA + cv) * 2),
                       &g_W[(size_t)(bn * BN + r) * KK + kc * KC + cv]);
        }
    };

    load_stage(0, 0);
    asm volatile("cp.async.commit_group;\n");
    load_stage(1, 1);
    asm volatile("cp.async.commit_group;\n");

    uint32_t af[2][2][4], bfr[2][8][2];   // double-buffered fragments

    for (int kc = 0; kc < KK / KC; kc++) {
        asm volatile("cp.async.wait_group 1;\n");   // stage kc resident
        __syncthreads();
        if (kc + 2 < KK / KC) load_stage(kc + 2, (kc + 2) % NST);
        asm volatile("cp.async.commit_group;\n");   // always commit (group counting)

        int st = kc % NST;
        uint32_t aStage = smem_u32 + (uint32_t)(st * A_STG * 2) + aBase;
        uint32_t wStage = smem_u32 + (uint32_t)((W_BASE + st * W_STG) * 2) + bBase;

        // preload fragments for step 0
        #pragma unroll
        for (int mt = 0; mt < 2; mt++)
            ldsm4(af[0][mt][0], af[0][mt][1], af[0][mt][2], af[0][mt][3],
                  aStage + (uint32_t)((mt * 16 * SA) * 2));
        #pragma unroll
        for (int p = 0; p < 4; p++)
            ldsm4(bfr[0][2 * p][0], bfr[0][2 * p][1], bfr[0][2 * p + 1][0], bfr[0][2 * p + 1][1],
                  wStage + (uint32_t)((p * 16 * SA) * 2));

        #pragma unroll
        for (int s = 0; s < KC / 16; s++) {
            int cur = s & 1, nxt = cur ^ 1;
            if (s + 1 < KC / 16) {       // prefetch next step's fragments
                int kb = (s + 1) * 16;
                #pragma unroll
                for (int mt = 0; mt < 2; mt++)
                    ldsm4(af[nxt][mt][0], af[nxt][mt][1], af[nxt][mt][2], af[nxt][mt][3],
                          aStage + (uint32_t)((mt * 16 * SA + kb) * 2));
                #pragma unroll
                for (int p = 0; p < 4; p++)
                    ldsm4(bfr[nxt][2 * p][0], bfr[nxt][2 * p][1],
                          bfr[nxt][2 * p + 1][0], bfr[nxt][2 * p + 1][1],
                          wStage + (uint32_t)((p * 16 * SA + kb) * 2));
            }
            #pragma unroll
            for (int mt = 0; mt < 2; mt++)
                #pragma unroll
                for (int nt = 0; nt < 8; nt++)
                    mma16816(acc[mt][nt], af[cur][mt], bfr[cur][nt]);
        }
    }

    // epilogue: add cterm, store fp16 scores, write per-(row, 64col) block max
    int n0 = bn * BN + wn * 64;
    float rmax[2][2] = {{NEG_INF, NEG_INF}, {NEG_INF, NEG_INF}};
    #pragma unroll
    for (int mt = 0; mt < 2; mt++) {
        int row0 = bm * BM + wm * 32 + mt * 16 + g;
        #pragma unroll
        for (int nt = 0; nt < 8; nt++) {
            int col = n0 + nt * 8 + t4 * 2;
            float2 ct = *(const float2*)&g_cterm[col];
            float v0 = acc[mt][nt][0] + ct.x;
            float v1 = acc[mt][nt][1] + ct.y;
            float v2 = acc[mt][nt][2] + ct.x;
            float v3 = acc[mt][nt][3] + ct.y;
            *(__half2*)&g_S[(size_t)row0 * KCL + col]       = __floats2half2_rn(v0, v1);
            *(__half2*)&g_S[(size_t)(row0 + 8) * KCL + col] = __floats2half2_rn(v2, v3);
            rmax[mt][0] = fmaxf(rmax[mt][0], fmaxf(v0, v1));
            rmax[mt][1] = fmaxf(rmax[mt][1], fmaxf(v2, v3));
        }
    }
    int blk = bn * 2 + wn;
    #pragma unroll
    for (int mt = 0; mt < 2; mt++)
        #pragma unroll
        for (int h = 0; h < 2; h++) {
            float v = rmax[mt][h];
            v = fmaxf(v, __shfl_xor_sync(0xffffffffu, v, 1));
            v = fmaxf(v, __shfl_xor_sync(0xffffffffu, v, 2));
            if (t4 == 0) {
                int row = bm * BM + wm * 32 + mt * 16 + h * 8 + g;
                g_blk[(size_t)row * NBLK + blk] = v;   // unique writer per (row, blk)
            }
        }
}

// ---------------- candidate selection via block-max order statistics ------
// theta_b (32nd-largest block max) <= 32nd-largest score. A true top-32 member
// has fp16 score >= theta_b - 2*err_gemm - 0.25 (fp16 ulp at |lp|~512).
// Margin 2.5 total: err_gemm budget 1.125 (~5-6 sigma of bf16 accumulation).
__global__ __launch_bounds__(256) void select_kernel() {
    int b = blockIdx.x;
    int tid = threadIdx.x, wid = tid >> 5, lane = tid & 31;
    __shared__ float blk[NBLK];
    __shared__ unsigned hist[2048];
    __shared__ float smax[8];
    __shared__ unsigned wsum[8];
    __shared__ int s_bin;
    __shared__ int s_cnt;

    for (int i = tid; i < NBLK; i += 256) blk[i] = g_blk[(size_t)b * NBLK + i];
    for (int i = tid; i < 2048; i += 256) hist[i] = 0u;
    if (tid == 0) { s_cnt = 0; s_bin = 2047; }
    __syncthreads();

    // row max over block maxima
    float m = NEG_INF;
    for (int i = tid; i < NBLK; i += 256) m = fmaxf(m, blk[i]);
    #pragma unroll
    for (int o = 16; o; o >>= 1) m = fmaxf(m, __shfl_xor_sync(0xffffffffu, m, o));
    if (lane == 0) smax[wid] = m;
    __syncthreads();
    float M = fmaxf(fmaxf(fmaxf(smax[0], smax[1]), fmaxf(smax[2], smax[3])),
                    fmaxf(fmaxf(smax[4], smax[5]), fmaxf(smax[6], smax[7])));

    // histogram of (M - blkmax), 0.125-wide bins, clamped to 2047
    for (int i = tid; i < NBLK; i += 256) {
        float d = M - blk[i];
        int bin = (int)(d * 8.0f);
        atomicAdd(&hist[min(bin, 2047)], 1u);
    }
    __syncthreads();

    // parallel search for first bin with cumulative >= TOPK
    unsigned seg = 0;
    #pragma unroll
    for (int j = 0; j < 8; j++) seg += hist[tid * 8 + j];
    unsigned inc = seg;
    #pragma unroll
    for (int o = 1; o < 32; o <<= 1) {
        unsigned n = __shfl_up_sync(0xffffffffu, inc, o);
        if (lane >= o) inc += n;
    }
    if (lane == 31) wsum[wid] = inc;
    __syncthreads();
    unsigned woff = 0;
    for (int q = 0; q < wid; q++) woff += wsum[q];
    unsigned incl = inc + woff;
    unsigned excl = incl - seg;
    if (excl < TOPK && incl >= TOPK) {   // unique crossing segment
        unsigned cum = excl;
        #pragma unroll
        for (int j = 0; j < 8; j++) {
            cum += hist[tid * 8 + j];
            if (cum >= TOPK) { s_bin = tid * 8 + j; break; }
        }
    }
    __syncthreads();

    float theta = M - (float)(s_bin + 1) * 0.125f;
    float Tc = theta - 2.5f;            // 0.25 fp16 + 2*1.125 gemm err margin
    float Tb = Tc - 0.25f;              // fp32 blkmax vs fp16 score slack

    for (int j = wid; j < NBLK; j += 8) {        // j uniform per warp
        if (blk[j] < Tb) continue;
        const __half2* p2 = (const __half2*)&g_S[(size_t)b * KCL + j * 64];
        float2 f = __half22float2(p2[lane]);
        int col = j * 64 + lane * 2;
        if (f.x >= Tc) {
            int p = atomicAdd(&s_cnt, 1);
            if (p < CAND_CAP) g_cand[(size_t)b * CAND_CAP + p] = col;
        }
        if (f.y >= Tc) {
            int p = atomicAdd(&s_cnt, 1);
            if (p < CAND_CAP) g_cand[(size_t)b * CAND_CAP + p] = col + 1;
        }
    }
    __syncthreads();
    if (tid == 0) g_cnt[b] = min(s_cnt, CAND_CAP);
}

// ---------------- prefix sum over per-row candidate counts ---------------
__global__ __launch_bounds__(1024) void prefix_kernel() {
    __shared__ int s[1024];
    int t = threadIdx.x;
    s[t] = g_cnt[t];
    __syncthreads();
    for (int o = 1; o < 1024; o <<= 1) {
        int v = (t >= o) ? s[t - o] : 0;
        __syncthreads();
        s[t] += v;
        __syncthreads();
    }
    g_pref[t + 1] = s[t];
    if (t == 0) g_pref[0] = 0;
}

// ---------------- flat exact-lp kernel: one warp per (row, candidate) ----
__global__ __launch_bounds__(256) void lp_kernel(const float* __restrict__ x,
                                                 const float* __restrict__ mean,
                                                 const float* __restrict__ stddev) {
    int wid = threadIdx.x >> 5, lane = threadIdx.x & 31;
    int gw = blockIdx.x * 8 + wid;            // global warp id, 8192 total
    int npairs = __ldg(&g_pref[BB]);

    for (int p = gw; p < npairs; p += 8192) {
        // binary search: b with pref[b] <= p < pref[b+1] (warp-uniform)
        int lo = 0, hi = BB;
        while (hi - lo > 1) {
            int mid = (lo + hi) >> 1;
            if (__ldg(&g_pref[mid]) <= p) lo = mid; else hi = mid;
        }
        int b = lo;
        int slot = p - __ldg(&g_pref[b]);
        int k = __ldg(&g_cand[(size_t)b * CAND_CAP + slot]);

        const float4* mp = (const float4*)&mean[(size_t)k * DD];
        const float4* sp = (const float4*)&stddev[(size_t)k * DD];
        const float4* xp = (const float4*)&x[(size_t)b * DD];
        float acc = 0.f;
        #pragma unroll
        for (int t = 0; t < 2; t++) {
            int i = lane + t * 32;            // float4 index 0..63
            float4 mv = __ldg(&mp[i]);
            float4 sv = __ldg(&sp[i]);
            float4 xv = __ldg(&xp[i]);
            float d0 = xv.x - mv.x, d1 = xv.y - mv.y;
            float d2 = xv.z - mv.z, d3 = xv.w - mv.w;
            acc += d0 * d0 * (1.0f / (sv.x * sv.x));
            acc += d1 * d1 * (1.0f / (sv.y * sv.y));
            acc += d2 * d2 * (1.0f / (sv.z * sv.z));
            acc += d3 * d3 * (1.0f / (sv.w * sv.w));
        }
        #pragma unroll
        for (int o = 16; o; o >>= 1) acc += __shfl_xor_sync(0xffffffffu, acc, o);
        if (lane == 0)
            g_lpbuf[(size_t)b * CAND_CAP + slot] =
                -0.5f * acc - __ldg(&g_logn[k]) - 128.0f * LOG2PI;
    }
}

// ---------------- finalize: top-32 (rank count) + softmax + gather -------
__global__ __launch_bounds__(256) void finalize_kernel(const float* __restrict__ outputs,
                                                       float* __restrict__ out) {
    int b = blockIdx.x;
    int tid = threadIdx.x;
    __shared__ float lp_s[CAND_CAP];
    __shared__ int   ck[CAND_CAP];
    __shared__ int   selk[TOPK];
    __shared__ float selw[TOPK];

    int cnt = g_cnt[b];
    for (int j = tid; j < cnt; j += 256) {
        lp_s[j] = g_lpbuf[(size_t)b * CAND_CAP + j];
        ck[j]   = g_cand[(size_t)b * CAND_CAP + j];
    }
    __syncthreads();

    // top-32 by rank counting (deterministic: ties broken by cluster id)
    for (int i = tid; i < cnt; i += 256) {
        float v = lp_s[i];
        int ki = ck[i];
        int rank = 0;
        for (int j = 0; j < cnt; j++) {
            float u = lp_s[j];
            rank += (u > v) || (u == v && ck[j] < ki);
            if (rank >= TOPK) break;
        }
        if (rank < TOPK) { selk[rank] = ki; selw[rank] = v; }
    }
    __syncthreads();

    // softmax over the 32 (rank 0 holds the max)
    if (tid == 0) {
        float m = selw[0], z = 0.f;
        #pragma unroll
        for (int i = 0; i < TOPK; i++) { float e = expf(selw[i] - m); selw[i] = e; z += e; }
        float iz = 1.0f / z;
        #pragma unroll
        for (int i = 0; i < TOPK; i++) selw[i] *= iz;
    }
    __syncthreads();

    // weighted gather: out[b, o] = sum_i w_i * outputs[k_i, o]
    float acc = 0.f;
    #pragma unroll 8
    for (int i = 0; i < TOPK; i++)
        acc += selw[i] * outputs[selk[i] * OO + tid];
    out[b * OO + tid] = acc;
}

// ---------------- launch -----------------------------------------------
extern "C" void kernel_launch(void* const* d_in, const int* in_sizes, int n_in,
                              void* d_out, int out_size) {
    const float* x       = (const float*)d_in[0];
    const float* mean    = (const float*)d_in[1];
    const float* stddev  = (const float*)d_in[2];
    const float* outputs = (const float*)d_in[3];
    float* out = (float*)d_out;
    (void)in_sizes; (void)n_in; (void)out_size;

    cudaFuncSetAttribute(gemm_kernel, cudaFuncAttributeMaxDynamicSharedMemorySize, SMEM_BYTES);

    prep_x_kernel<<<BB, 256>>>(x);
    prep_w_kernel<<<KCL / 8, 256>>>(mean, stddev);
    gemm_kernel<<<dim3(BB / BM, KCL / BN), 256, SMEM_BYTES>>>();
    select_kernel<<<BB, 256>>>();
    prefix_kernel<<<1, 1024>>>();
    lp_kernel<<<1024, 256>>>(x, mean, stddev);
    finalize_kernel<<<BB, 256>>>(outputs, out);
}

// round 13
// speedup vs baseline: 1.9391x; 1.3662x over previous
#include <cuda_runtime.h>
#include <cuda_bf16.h>
#include <cuda_fp16.h>
#include <cstdint>

// Problem constants (fixed by setup_inputs)
#define KCL 65536      // number of clusters (GEMM N)
#define DD  256        // feature dim
#define OO  256        // output dim
#define BB  1024       // batch rows (GEMM M)
#define TOPK 32
#define KK  512        // GEMM reduction dim (2*DD)
#define CAND_CAP 2048
#define NBLK (KCL / 64)    // 1024 score-blocks of 64 cols per row

// ---------------- scratch (static device globals; no allocations) ----------
__device__ __nv_bfloat16 g_W[(size_t)KCL * KK];          // 64 MB
__device__ __nv_bfloat16 g_A[(size_t)BB * KK];           // 1 MB
__device__ float g_cterm[KCL];
__device__ float g_logn[KCL];
__device__ __half g_S[(size_t)BB * KCL];                 // 128 MB fp16 scores
__device__ float g_blk[(size_t)BB * NBLK];               // 4 MB per-64col block maxima
__device__ int g_cand[(size_t)BB * CAND_CAP];
__device__ float g_lpbuf[(size_t)BB * CAND_CAP];         // 8 MB exact lp per candidate
__device__ int g_cnt[BB];
__device__ int g_pref[BB + 1];
__device__ int g_unitvar;   // 1 iff every stddev element == 1.0f

#define NEG_INF (__int_as_float(0xff800000))
#define LOG2PI 1.8378770664093455f

// ---------------- prep A = [x*x, x] (bf16) ------------------------------
__global__ void prep_x_kernel(const float* __restrict__ x) {
    int b = blockIdx.x;
    int d = threadIdx.x;
    if (b == 0 && d == 0) g_unitvar = 1;   // reset; prep_w may clear (stream-ordered)
    float v = x[b * DD + d];
    g_A[b * KK + d]      = __float2bfloat16(v * v);
    g_A[b * KK + DD + d] = __float2bfloat16(v);
}

// ---------------- prep W: one warp per cluster, 8 clusters per block ------
__global__ __launch_bounds__(256) void prep_w_kernel(const float* __restrict__ mean,
                                                     const float* __restrict__ stddev) {
    int k = blockIdx.x * 8 + (threadIdx.x >> 5);
    int lane = threadIdx.x & 31;
    const float* mp = &mean[(size_t)k * DD];
    const float* sp = &stddev[(size_t)k * DD];
    __nv_bfloat16* w0 = &g_W[(size_t)k * KK];

    float s1 = 0.f, s2 = 0.f;
    bool unit = true;
    #pragma unroll
    for (int t = 0; t < 8; t++) {
        int d = lane + t * 32;
        float mu = mp[d];
        float sg = sp[d];
        unit &= (sg == 1.0f);
        float iv = __fdividef(1.0f, sg * sg);
        w0[d]      = __float2bfloat16(-0.5f * iv);
        w0[DD + d] = __float2bfloat16(mu * iv);
        s1 += mu * mu * iv;
        s2 += __logf(sg);
    }
    if (!unit) g_unitvar = 0;   // benign race: all writers store 0
    #pragma unroll
    for (int o = 16; o; o >>= 1) {
        s1 += __shfl_xor_sync(0xffffffffu, s1, o);
        s2 += __shfl_xor_sync(0xffffffffu, s2, o);
    }
    if (lane == 0) {
        g_logn[k]  = s2;
        g_cterm[k] = -0.5f * s1 - s2 - 128.0f * LOG2PI;
    }
}

// ---------------- bf16 mma GEMM: S = A @ W^T + cterm --------------------
// If g_unitvar: the x^2 * (-0.5*ivar) half contributes a per-row constant
// (top-k and softmax invariant) -> skip k-chunks 0..3, GEMM K halves to 256.
#define BM 128
#define BN 128
#define KC 64
#define NST 3
#define SA 72   // padded smem stride (elems); conflict-free ldmatrix

#define A_STG (BM * SA)                 // elems per A stage
#define W_STG (BN * SA)
#define W_BASE (NST * A_STG)            // layout: [A0][A1][A2][W0][W1][W2]
#define SMEM_BYTES ((NST * A_STG + NST * W_STG) * 2)   // 110,592 B -> 2 CTAs/SM

__device__ __forceinline__ void mma16816(float* c, const uint32_t* a, const uint32_t* b) {
    asm volatile(
        "mma.sync.aligned.m16n8k16.row.col.f32.bf16.bf16.f32 "
        "{%0,%1,%2,%3}, {%4,%5,%6,%7}, {%8,%9}, {%0,%1,%2,%3};\n"
        : "+f"(c[0]), "+f"(c[1]), "+f"(c[2]), "+f"(c[3])
        : "r"(a[0]), "r"(a[1]), "r"(a[2]), "r"(a[3]), "r"(b[0]), "r"(b[1]));
}

__device__ __forceinline__ void ldsm4(uint32_t& r0, uint32_t& r1, uint32_t& r2, uint32_t& r3,
                                      uint32_t addr) {
    asm volatile("ldmatrix.sync.aligned.m8n8.x4.shared.b16 {%0,%1,%2,%3}, [%4];\n"
                 : "=r"(r0), "=r"(r1), "=r"(r2), "=r"(r3) : "r"(addr));
}

__device__ __forceinline__ void cp_async16(uint32_t smem_dst, const void* gmem_src) {
    asm volatile("cp.async.cg.shared.global [%0], [%1], 16;\n" :: "r"(smem_dst), "l"(gmem_src));
}

__global__ __launch_bounds__(256, 2) void gemm_kernel() {
    extern __shared__ __nv_bfloat16 sh[];
    uint32_t smem_u32 = (uint32_t)__cvta_generic_to_shared(sh);

    int bm = blockIdx.x;              // 0..7   (fast dim -> W tile reused across bm in L2)
    int bn = blockIdx.y;              // 0..511
    int tid = threadIdx.x;
    int wid = tid >> 5, lane = tid & 31;
    int wm = wid & 3, wn = wid >> 2;  // warp tile: rows wm*32, cols wn*64
    int g = lane >> 2, t4 = lane & 3;

    int kc0 = g_unitvar ? (KK / KC / 2) : 0;   // uniform across grid

    // per-thread LDSM address components (bytes, relative to stage base)
    uint32_t aBase = (uint32_t)(((wm * 32 + (lane & 15)) * SA + (lane >> 4) * 8) * 2);
    uint32_t bBase = (uint32_t)(((wn * 64 + (lane & 7) + ((lane >> 4) << 3)) * SA
                                 + ((lane >> 3) & 1) * 8) * 2);

    int r0v = tid >> 3;               // rows step 32 per j
    int cv  = (tid & 7) * 8;          // col elems

    float acc[2][8][4];
    #pragma unroll
    for (int mt = 0; mt < 2; mt++)
        #pragma unroll
        for (int nt = 0; nt < 8; nt++)
            #pragma unroll
            for (int i = 0; i < 4; i++) acc[mt][nt][i] = 0.f;

    auto load_stage = [&](int kc, int st) {
        uint32_t aDst = smem_u32 + (uint32_t)(st * A_STG * 2);
        uint32_t wDst = smem_u32 + (uint32_t)((W_BASE + st * W_STG) * 2);
        #pragma unroll
        for (int j = 0; j < 4; j++) {
            int r = r0v + j * 32;
            cp_async16(aDst + (uint32_t)((r * SA + cv) * 2),
                       &g_A[(size_t)(bm * BM + r) * KK + kc * KC + cv]);
            cp_async16(wDst + (uint32_t)((r * SA + cv) * 2),
                       &g_W[(size_t)(bn * BN + r) * KK + kc * KC + cv]);
        }
    };

    load_stage(kc0, 0);
    asm volatile("cp.async.commit_group;\n");
    load_stage(kc0 + 1, 1);
    asm volatile("cp.async.commit_group;\n");

    uint32_t af[2][2][4], bfr[2][8][2];   // double-buffered fragments

    for (int kc = kc0; kc < KK / KC; kc++) {
        asm volatile("cp.async.wait_group 1;\n");   // stage kc resident
        __syncthreads();
        if (kc + 2 < KK / KC) load_stage(kc + 2, (kc + 2 - kc0) % NST);
        asm volatile("cp.async.commit_group;\n");   // always commit (group counting)

        int st = (kc - kc0) % NST;
        uint32_t aStage = smem_u32 + (uint32_t)(st * A_STG * 2) + aBase;
        uint32_t wStage = smem_u32 + (uint32_t)((W_BASE + st * W_STG) * 2) + bBase;

        // preload fragments for step 0
        #pragma unroll
        for (int mt = 0; mt < 2; mt++)
            ldsm4(af[0][mt][0], af[0][mt][1], af[0][mt][2], af[0][mt][3],
                  aStage + (uint32_t)((mt * 16 * SA) * 2));
        #pragma unroll
        for (int p = 0; p < 4; p++)
            ldsm4(bfr[0][2 * p][0], bfr[0][2 * p][1], bfr[0][2 * p + 1][0], bfr[0][2 * p + 1][1],
                  wStage + (uint32_t)((p * 16 * SA) * 2));

        #pragma unroll
        for (int s = 0; s < KC / 16; s++) {
            int cur = s & 1, nxt = cur ^ 1;
            if (s + 1 < KC / 16) {       // prefetch next step's fragments
                int kb = (s + 1) * 16;
                #pragma unroll
                for (int mt = 0; mt < 2; mt++)
                    ldsm4(af[nxt][mt][0], af[nxt][mt][1], af[nxt][mt][2], af[nxt][mt][3],
                          aStage + (uint32_t)((mt * 16 * SA + kb) * 2));
                #pragma unroll
                for (int p = 0; p < 4; p++)
                    ldsm4(bfr[nxt][2 * p][0], bfr[nxt][2 * p][1],
                          bfr[nxt][2 * p + 1][0], bfr[nxt][2 * p + 1][1],
                          wStage + (uint32_t)((p * 16 * SA + kb) * 2));
            }
            #pragma unroll
            for (int mt = 0; mt < 2; mt++)
                #pragma unroll
                for (int nt = 0; nt < 8; nt++)
                    mma16816(acc[mt][nt], af[cur][mt], bfr[cur][nt]);
        }
    }

    // epilogue: add cterm, store fp16 scores, write per-(row, 64col) block max
    int n0 = bn * BN + wn * 64;
    float rmax[2][2] = {{NEG_INF, NEG_INF}, {NEG_INF, NEG_INF}};
    #pragma unroll
    for (int mt = 0; mt < 2; mt++) {
        int row0 = bm * BM + wm * 32 + mt * 16 + g;
        #pragma unroll
        for (int nt = 0; nt < 8; nt++) {
            int col = n0 + nt * 8 + t4 * 2;
            float2 ct = *(const float2*)&g_cterm[col];
            float v0 = acc[mt][nt][0] + ct.x;
            float v1 = acc[mt][nt][1] + ct.y;
            float v2 = acc[mt][nt][2] + ct.x;
            float v3 = acc[mt][nt][3] + ct.y;
            *(__half2*)&g_S[(size_t)row0 * KCL + col]       = __floats2half2_rn(v0, v1);
            *(__half2*)&g_S[(size_t)(row0 + 8) * KCL + col] = __floats2half2_rn(v2, v3);
            rmax[mt][0] = fmaxf(rmax[mt][0], fmaxf(v0, v1));
            rmax[mt][1] = fmaxf(rmax[mt][1], fmaxf(v2, v3));
        }
    }
    int blk = bn * 2 + wn;
    #pragma unroll
    for (int mt = 0; mt < 2; mt++)
        #pragma unroll
        for (int h = 0; h < 2; h++) {
            float v = rmax[mt][h];
            v = fmaxf(v, __shfl_xor_sync(0xffffffffu, v, 1));
            v = fmaxf(v, __shfl_xor_sync(0xffffffffu, v, 2));
            if (t4 == 0) {
                int row = bm * BM + wm * 32 + mt * 16 + h * 8 + g;
                g_blk[(size_t)row * NBLK + blk] = v;   // unique writer per (row, blk)
            }
        }
}

// ---------------- candidate selection via block-max order statistics ------
// theta_b (32nd-largest block max) <= 32nd-largest score. A true top-32 member
// has fp16 score >= theta_b - 2*err_gemm - 0.25 (fp16 ulp at |lp|~512).
__global__ __launch_bounds__(256) void select_kernel() {
    int b = blockIdx.x;
    int tid = threadIdx.x, wid = tid >> 5, lane = tid & 31;
    __shared__ float blk[NBLK];
    __shared__ unsigned hist[2048];
    __shared__ float smax[8];
    __shared__ unsigned wsum[8];
    __shared__ int s_bin;
    __shared__ int s_cnt;

    for (int i = tid; i < NBLK; i += 256) blk[i] = g_blk[(size_t)b * NBLK + i];
    for (int i = tid; i < 2048; i += 256) hist[i] = 0u;
    if (tid == 0) { s_cnt = 0; s_bin = 2047; }
    __syncthreads();

    // row max over block maxima
    float m = NEG_INF;
    for (int i = tid; i < NBLK; i += 256) m = fmaxf(m, blk[i]);
    #pragma unroll
    for (int o = 16; o; o >>= 1) m = fmaxf(m, __shfl_xor_sync(0xffffffffu, m, o));
    if (lane == 0) smax[wid] = m;
    __syncthreads();
    float M = fmaxf(fmaxf(fmaxf(smax[0], smax[1]), fmaxf(smax[2], smax[3])),
                    fmaxf(fmaxf(smax[4], smax[5]), fmaxf(smax[6], smax[7])));

    // histogram of (M - blkmax), 0.125-wide bins, clamped to 2047
    for (int i = tid; i < NBLK; i += 256) {
        float d = M - blk[i];
        int bin = (int)(d * 8.0f);
        atomicAdd(&hist[min(bin, 2047)], 1u);
    }
    __syncthreads();

    // parallel search for first bin with cumulative >= TOPK
    unsigned seg = 0;
    #pragma unroll
    for (int j = 0; j < 8; j++) seg += hist[tid * 8 + j];
    unsigned inc = seg;
    #pragma unroll
    for (int o = 1; o < 32; o <<= 1) {
        unsigned n = __shfl_up_sync(0xffffffffu, inc, o);
        if (lane >= o) inc += n;
    }
    if (lane == 31) wsum[wid] = inc;
    __syncthreads();
    unsigned woff = 0;
    for (int q = 0; q < wid; q++) woff += wsum[q];
    unsigned incl = inc + woff;
    unsigned excl = incl - seg;
    if (excl < TOPK && incl >= TOPK) {   // unique crossing segment
        unsigned cum = excl;
        #pragma unroll
        for (int j = 0; j < 8; j++) {
            cum += hist[tid * 8 + j];
            if (cum >= TOPK) { s_bin = tid * 8 + j; break; }
        }
    }
    __syncthreads();

    float theta = M - (float)(s_bin + 1) * 0.125f;
    float Tc = theta - 2.5f;            // 0.25 fp16 + 2*1.125 gemm err margin
    float Tb = Tc - 0.25f;              // fp32 blkmax vs fp16 score slack

    for (int j = wid; j < NBLK; j += 8) {        // j uniform per warp
        if (blk[j] < Tb) continue;
        const __half2* p2 = (const __half2*)&g_S[(size_t)b * KCL + j * 64];
        float2 f = __half22float2(p2[lane]);
        int col = j * 64 + lane * 2;
        if (f.x >= Tc) {
            int p = atomicAdd(&s_cnt, 1);
            if (p < CAND_CAP) g_cand[(size_t)b * CAND_CAP + p] = col;
        }
        if (f.y >= Tc) {
            int p = atomicAdd(&s_cnt, 1);
            if (p < CAND_CAP) g_cand[(size_t)b * CAND_CAP + p] = col + 1;
        }
    }
    __syncthreads();
    if (tid == 0) g_cnt[b] = min(s_cnt, CAND_CAP);
}

// ---------------- prefix sum over per-row candidate counts ---------------
__global__ __launch_bounds__(1024) void prefix_kernel() {
    __shared__ int s[1024];
    int t = threadIdx.x;
    s[t] = g_cnt[t];
    __syncthreads();
    for (int o = 1; o < 1024; o <<= 1) {
        int v = (t >= o) ? s[t - o] : 0;
        __syncthreads();
        s[t] += v;
        __syncthreads();
    }
    g_pref[t + 1] = s[t];
    if (t == 0) g_pref[0] = 0;
}

// ---------------- flat exact-lp kernel: one warp per (row, candidate) ----
__global__ __launch_bounds__(256) void lp_kernel(const float* __restrict__ x,
                                                 const float* __restrict__ mean,
                                                 const float* __restrict__ stddev) {
    int wid = threadIdx.x >> 5, lane = threadIdx.x & 31;
    int gw = blockIdx.x * 8 + wid;            // global warp id, 8192 total
    int npairs = __ldg(&g_pref[BB]);

    for (int p = gw; p < npairs; p += 8192) {
        // binary search: b with pref[b] <= p < pref[b+1] (warp-uniform)
        int lo = 0, hi = BB;
        while (hi - lo > 1) {
            int mid = (lo + hi) >> 1;
            if (__ldg(&g_pref[mid]) <= p) lo = mid; else hi = mid;
        }
        int b = lo;
        int slot = p - __ldg(&g_pref[b]);
        int k = __ldg(&g_cand[(size_t)b * CAND_CAP + slot]);

        const float4* mp = (const float4*)&mean[(size_t)k * DD];
        const float4* sp = (const float4*)&stddev[(size_t)k * DD];
        const float4* xp = (const float4*)&x[(size_t)b * DD];
        float acc = 0.f;
        #pragma unroll
        for (int t = 0; t < 2; t++) {
            int i = lane + t * 32;            // float4 index 0..63
            float4 mv = __ldg(&mp[i]);
            float4 sv = __ldg(&sp[i]);
            float4 xv = __ldg(&xp[i]);
            float d0 = xv.x - mv.x, d1 = xv.y - mv.y;
            float d2 = xv.z - mv.z, d3 = xv.w - mv.w;
            acc += d0 * d0 * (1.0f / (sv.x * sv.x));
            acc += d1 * d1 * (1.0f / (sv.y * sv.y));
            acc += d2 * d2 * (1.0f / (sv.z * sv.z));
            acc += d3 * d3 * (1.0f / (sv.w * sv.w));
        }
        #pragma unroll
        for (int o = 16; o; o >>= 1) acc += __shfl_xor_sync(0xffffffffu, acc, o);
        if (lane == 0)
            g_lpbuf[(size_t)b * CAND_CAP + slot] =
                -0.5f * acc - __ldg(&g_logn[k]) - 128.0f * LOG2PI;
    }
}

// ---------------- finalize: top-32 (rank count) + softmax + gather -------
__global__ __launch_bounds__(256) void finalize_kernel(const float* __restrict__ outputs,
                                                       float* __restrict__ out) {
    int b = blockIdx.x;
    int tid = threadIdx.x;
    __shared__ float lp_s[CAND_CAP];
    __shared__ int   ck[CAND_CAP];
    __shared__ int   selk[TOPK];
    __shared__ float selw[TOPK];

    int cnt = g_cnt[b];
    for (int j = tid; j < cnt; j += 256) {
        lp_s[j] = g_lpbuf[(size_t)b * CAND_CAP + j];
        ck[j]   = g_cand[(size_t)b * CAND_CAP + j];
    }
    __syncthreads();

    // top-32 by rank counting (deterministic: ties broken by cluster id)
    for (int i = tid; i < cnt; i += 256) {
        float v = lp_s[i];
        int ki = ck[i];
        int rank = 0;
        for (int j = 0; j < cnt; j++) {
            float u = lp_s[j];
            rank += (u > v) || (u == v && ck[j] < ki);
            if (rank >= TOPK) break;
        }
        if (rank < TOPK) { selk[rank] = ki; selw[rank] = v; }
    }
    __syncthreads();

    // softmax over the 32 (rank 0 holds the max)
    if (tid == 0) {
        float m = selw[0], z = 0.f;
        #pragma unroll
        for (int i = 0; i < TOPK; i++) { float e = expf(selw[i] - m); selw[i] = e; z += e; }
        float iz = 1.0f / z;
        #pragma unroll
        for (int i = 0; i < TOPK; i++) selw[i] *= iz;
    }
    __syncthreads();

    // weighted gather: out[b, o] = sum_i w_i * outputs[k_i, o]
    float acc = 0.f;
    #pragma unroll 8
    for (int i = 0; i < TOPK; i++)
        acc += selw[i] * outputs[selk[i] * OO + tid];
    out[b * OO + tid] = acc;
}

// ---------------- launch -----------------------------------------------
extern "C" void kernel_launch(void* const* d_in, const int* in_sizes, int n_in,
                              void* d_out, int out_size) {
    const float* x       = (const float*)d_in[0];
    const float* mean    = (const float*)d_in[1];
    const float* stddev  = (const float*)d_in[2];
    const float* outputs = (const float*)d_in[3];
    float* out = (float*)d_out;
    (void)in_sizes; (void)n_in; (void)out_size;

    cudaFuncSetAttribute(gemm_kernel, cudaFuncAttributeMaxDynamicSharedMemorySize, SMEM_BYTES);

    prep_x_kernel<<<BB, 256>>>(x);
    prep_w_kernel<<<KCL / 8, 256>>>(mean, stddev);
    gemm_kernel<<<dim3(BB / BM, KCL / BN), 256, SMEM_BYTES>>>();
    select_kernel<<<BB, 256>>>();
    prefix_kernel<<<1, 1024>>>();
    lp_kernel<<<1024, 256>>>(x, mean, stddev);
    finalize_kernel<<<BB, 256>>>(outputs, out);
}